// round 13
// baseline (speedup 1.0000x reference)
#include <cuda_runtime.h>
#include <cuda_fp16.h>
#include <cstdint>

// Problem constants
#define BN   4
#define SN   1024
#define MTOK (BN * SN)   // 4096

// ---------------------------------------------------------------------------
// Device scratch
// ---------------------------------------------------------------------------
__device__ float g_t    [MTOK * 1024];
__device__ float g_x1   [MTOK * 1024];
__device__ float g_x2   [MTOK * 1024];
__device__ float g_h    [MTOK * 4096];   // reused as half[MTOK*4096] (hidden)

__device__ __half g_qkv1h[MTOK * 3072];
__device__ __half g_q2h  [MTOK * 1024];
__device__ __half g_kv2h [MTOK * 2048];
__device__ __half g_abuf [MTOK * 1024];
__device__ __half g_ench [MTOK * 1024];

// fp16 weights (transposed to [N x K] row-major)
__device__ __half g_wqkv1p[3072 * 1024];
__device__ __half g_wo1p  [1024 * 1024];
__device__ __half g_wq2p  [1024 * 1024];
__device__ __half g_wkv2p [2048 * 1024];
__device__ __half g_wo2p  [1024 * 1024];
__device__ __half g_w1fp  [4096 * 1024];
__device__ __half g_w2fp  [1024 * 4096];

// ---------------------------------------------------------------------------
// PTX helpers
// ---------------------------------------------------------------------------
__device__ __forceinline__ uint32_t smem_u32(const void* p) {
    uint32_t a;
    asm("{ .reg .u64 t; cvta.to.shared.u64 t, %1; cvt.u32.u64 %0, t; }"
        : "=r"(a) : "l"(p));
    return a;
}

__device__ __forceinline__ void cpasync16(uint32_t dst, const void* src) {
    asm volatile("cp.async.cg.shared.global [%0], [%1], 16;"
                 :: "r"(dst), "l"(src));
}

__device__ __forceinline__ void ldsm4(uint32_t& r0, uint32_t& r1,
                                      uint32_t& r2, uint32_t& r3, uint32_t a) {
    asm volatile("ldmatrix.sync.aligned.m8n8.x4.shared.b16 {%0,%1,%2,%3}, [%4];"
                 : "=r"(r0), "=r"(r1), "=r"(r2), "=r"(r3) : "r"(a));
}

__device__ __forceinline__ void ldsm4t(uint32_t& r0, uint32_t& r1,
                                       uint32_t& r2, uint32_t& r3, uint32_t a) {
    asm volatile("ldmatrix.sync.aligned.m8n8.x4.trans.shared.b16 {%0,%1,%2,%3}, [%4];"
                 : "=r"(r0), "=r"(r1), "=r"(r2), "=r"(r3) : "r"(a));
}

__device__ __forceinline__ void mma16816(float* c, const uint32_t* a,
                                         uint32_t b0, uint32_t b1) {
    asm volatile(
        "mma.sync.aligned.m16n8k16.row.col.f32.f16.f16.f32 "
        "{%0,%1,%2,%3}, {%4,%5,%6,%7}, {%8,%9}, {%0,%1,%2,%3};"
        : "+f"(c[0]), "+f"(c[1]), "+f"(c[2]), "+f"(c[3])
        : "r"(a[0]), "r"(a[1]), "r"(a[2]), "r"(a[3]), "r"(b0), "r"(b1));
}

__device__ __forceinline__ uint32_t packh2(float a, float b) {
    __half2 h = __floats2half2_rn(a, b);
    return *(uint32_t*)&h;
}

// ---------------------------------------------------------------------------
// Batched weight transpose+convert: 10 jobs in ONE launch.
// ---------------------------------------------------------------------------
struct WJob {
    const float* X; __half* Y;
    int K, Nin, rowOff, tilesX, tilesPerHead, count;
    long hStride;
};
struct WJobs { WJob j[10]; };

__global__ __launch_bounds__(256)
void convw(WJobs jobs) {
    int t = blockIdx.x;
    int i = 0;
    while (i < 9 && t >= jobs.j[i].count) { t -= jobs.j[i].count; i++; }
    const WJob jb = jobs.j[i];
    const int h = t / jb.tilesPerHead;
    const int rem = t % jb.tilesPerHead;
    const int ky = rem / jb.tilesX, nx = rem % jb.tilesX;
    const float* X = jb.X + (long)h * jb.hStride;
    const int rowOff = jb.rowOff + h * jb.Nin;
    const int n0 = nx * 32, k0 = ky * 32;

    __shared__ float tl[32][33];
    const int tx = threadIdx.x & 31, ty = threadIdx.x >> 5;
#pragma unroll
    for (int r = 0; r < 4; r++)
        tl[ty + 8 * r][tx] = X[(long)(k0 + ty + 8 * r) * jb.Nin + n0 + tx];
    __syncthreads();
#pragma unroll
    for (int r = 0; r < 4; r++) {
        const int n = n0 + ty + 8 * r, k = k0 + tx;
        jb.Y[(long)(rowOff + n) * jb.K + k] = __float2half_rn(tl[tx][ty + 8 * r]);
    }
}

// ---------------------------------------------------------------------------
// Convert activations: X fp32 [n] -> Y fp16 [n]
// ---------------------------------------------------------------------------
__global__ __launch_bounds__(256)
void converta(const float* __restrict__ X, __half* __restrict__ Y) {
    const size_t i = ((size_t)blockIdx.x * 256 + threadIdx.x) << 3;
    float4 a = *(const float4*)&X[i];
    float4 b = *(const float4*)&X[i + 4];
    __half2 h0 = __floats2half2_rn(a.x, a.y);
    __half2 h1 = __floats2half2_rn(a.z, a.w);
    __half2 h2 = __floats2half2_rn(b.x, b.y);
    __half2 h3 = __floats2half2_rn(b.z, b.w);
    uint4 u;
    u.x = *(unsigned*)&h0; u.y = *(unsigned*)&h1;
    u.z = *(unsigned*)&h2; u.w = *(unsigned*)&h3;
    *(uint4*)&Y[i] = u;
}

// ---------------------------------------------------------------------------
// HMMA fp16 GEMM v4: CTA tile 128x64, 8 warps (4x2), warptile 32x32,
// K-step 32, 4-stage cp.async, 3 CTAs/SM (24 warps/SM target).
// OUT: 0 = fp32 C32 (pitch N); 1 = fp16 C16 (pitch P2).
// SEG: bias selected per 1024-col segment from {b0, b1v, b2}.
// ---------------------------------------------------------------------------
#define SMP 40
#define ASTG (128 * SMP)
#define BSTG (64 * SMP)
#define GSMEM (4 * (ASTG + BSTG) * 2)   // 61440 B

template<bool RELU, bool RES, int OUT, bool SEG>
__global__ __launch_bounds__(256, 3)
void gemm_mma(const __half* __restrict__ A, const __half* __restrict__ Bw,
              const float* __restrict__ b0, const float* __restrict__ b1v,
              const float* __restrict__ b2, const float* __restrict__ R,
              float* __restrict__ C32, __half* __restrict__ C16,
              int N, int Kp, int P2) {
    extern __shared__ __half smh[];
    __half* As = smh;                       // [4][128*SMP]
    __half* Bs = smh + 4 * ASTG;            // [4][64*SMP]

    const int tid = threadIdx.x, lane = tid & 31, warp = tid >> 5;
    const int m0 = blockIdx.x * 128, n0 = blockIdx.y * 64;
    const int wm = (warp & 3) * 32, wn = (warp >> 2) * 32;

    const uint32_t asb = smem_u32(As);
    const uint32_t bsb = smem_u32(Bs);
    const __half* Ab = A + (size_t)m0 * Kp;
    const __half* Bb = Bw + (size_t)n0 * Kp;

    float acc[2][4][4];
#pragma unroll
    for (int i = 0; i < 2; i++)
#pragma unroll
        for (int j = 0; j < 4; j++)
#pragma unroll
            for (int k = 0; k < 4; k++) acc[i][j][k] = 0.f;

    // Stage = A 128x32 halfs (4x16B segs/row) + B 64x32.
#define LOAD_STAGE(s, k0) do {                                                  \
        _Pragma("unroll")                                                       \
        for (int i_ = 0; i_ < 2; i_++) {                                        \
            int idx_ = tid + (i_ << 8);                                         \
            int rr_ = idx_ >> 2, sg_ = idx_ & 3;                                \
            cpasync16(asb + (uint32_t)(((s) * ASTG + rr_ * SMP + sg_ * 8) * 2), \
                      Ab + (size_t)rr_ * Kp + (size_t)(k0) + sg_ * 8);          \
        }                                                                       \
        {                                                                       \
            int rr_ = tid >> 2, sg_ = tid & 3;                                  \
            if (rr_ < 64)                                                       \
                cpasync16(bsb + (uint32_t)(((s) * BSTG + rr_ * SMP + sg_ * 8) * 2), \
                          Bb + (size_t)rr_ * Kp + (size_t)(k0) + sg_ * 8);      \
        }                                                                       \
        asm volatile("cp.async.commit_group;" ::: "memory");                    \
    } while (0)

    const int nst = Kp >> 5;
    LOAD_STAGE(0, 0);
    LOAD_STAGE(1, 32);
    LOAD_STAGE(2, 64);

    for (int kt = 0; kt < nst; kt++) {
        if (kt + 2 < nst)
            asm volatile("cp.async.wait_group 2;" ::: "memory");
        else if (kt + 1 < nst)
            asm volatile("cp.async.wait_group 1;" ::: "memory");
        else
            asm volatile("cp.async.wait_group 0;" ::: "memory");
        __syncthreads();

        if (kt + 3 < nst)
            LOAD_STAGE((kt + 3) & 3, (kt + 3) << 5);

        const uint32_t sA = asb + (uint32_t)((kt & 3) * ASTG * 2);
        const uint32_t sB = bsb + (uint32_t)((kt & 3) * BSTG * 2);

#pragma unroll
        for (int kk = 0; kk < 2; kk++) {
            uint32_t aF[2][4], bF[2][4];
#pragma unroll
            for (int mt = 0; mt < 2; mt++) {
                uint32_t ad = sA + (uint32_t)(((wm + mt * 16 + (lane & 15)) * SMP
                                  + kk * 16 + (lane >> 4) * 8) * 2);
                ldsm4(aF[mt][0], aF[mt][1], aF[mt][2], aF[mt][3], ad);
            }
#pragma unroll
            for (int g = 0; g < 2; g++) {
                int nr = wn + g * 16 + (lane & 7) + ((lane >> 4) << 3);
                int kc = kk * 16 + ((lane >> 3) & 1) * 8;
                uint32_t bd = sB + (uint32_t)((nr * SMP + kc) * 2);
                ldsm4(bF[g][0], bF[g][1], bF[g][2], bF[g][3], bd);
            }
#pragma unroll
            for (int mt = 0; mt < 2; mt++)
#pragma unroll
                for (int nt = 0; nt < 4; nt++)
                    mma16816(acc[mt][nt], aF[mt],
                             bF[nt >> 1][(nt & 1) * 2],
                             bF[nt >> 1][(nt & 1) * 2 + 1]);
        }
    }
#undef LOAD_STAGE

    const float* bias = b0;
    int cb0 = n0;
    if (SEG) {
        const int sg = n0 >> 10;
        bias = (sg == 0) ? b0 : ((sg == 1) ? b1v : b2);
        cb0 = n0 & 1023;
    }

    // Epilogue: each warp owns 32 rows x 32 cols
#pragma unroll
    for (int mt = 0; mt < 2; mt++) {
        const int r0 = m0 + wm + mt * 16 + (lane >> 2);
#pragma unroll
        for (int nt = 0; nt < 4; nt++) {
            const int cl = wn + nt * 8 + ((lane & 3) << 1);
            const int c = n0 + cl;
            float2 bv = *(const float2*)&bias[cb0 + cl];
            float2 v0, v1;
            v0.x = acc[mt][nt][0] + bv.x; v0.y = acc[mt][nt][1] + bv.y;
            v1.x = acc[mt][nt][2] + bv.x; v1.y = acc[mt][nt][3] + bv.y;
            if (RES) {
                float2 ra = *(const float2*)&R[(size_t)r0 * N + c];
                float2 rb = *(const float2*)&R[(size_t)(r0 + 8) * N + c];
                v0.x += ra.x; v0.y += ra.y;
                v1.x += rb.x; v1.y += rb.y;
            }
            if (RELU) {
                v0.x = fmaxf(v0.x, 0.f); v0.y = fmaxf(v0.y, 0.f);
                v1.x = fmaxf(v1.x, 0.f); v1.y = fmaxf(v1.y, 0.f);
            }
            if (OUT == 0) {
                *(float2*)&C32[(size_t)r0 * N + c] = v0;
                *(float2*)&C32[(size_t)(r0 + 8) * N + c] = v1;
            } else {
                __half2 h0 = __floats2half2_rn(v0.x, v0.y);
                __half2 h1 = __floats2half2_rn(v1.x, v1.y);
                *(__half2*)&C16[(size_t)r0 * P2 + c] = h0;
                *(__half2*)&C16[(size_t)(r0 + 8) * P2 + c] = h1;
            }
        }
    }
}

// ---------------------------------------------------------------------------
// HMMA fp16 flash attention, double-buffered cp.async K/V pipeline.
// ---------------------------------------------------------------------------
__global__ __launch_bounds__(128)
void attn_h(const __half* __restrict__ Qp, int ldq,
            const __half* __restrict__ Kp, int ldk,
            const __half* __restrict__ Vp, int ldv,
            __half* __restrict__ Op, int causal) {
    __shared__ __half Qs[64 * 72];
    __shared__ __half Ks[2][64 * 72];
    __shared__ __half Vs[2][64 * 72];

    const int tid = threadIdx.x, lane = tid & 31, warp = tid >> 5;
    const int q0 = blockIdx.x * 64;
    const int b = blockIdx.y >> 4, h = blockIdx.y & 15;

    const __half* qb = Qp + (size_t)(b * SN) * ldq + h * 64;
    const __half* kb = Kp + (size_t)(b * SN) * ldk + h * 64;
    const __half* vb = Vp + (size_t)(b * SN) * ldv + h * 64;

    const uint32_t ksb = smem_u32(Ks);
    const uint32_t vsb = smem_u32(Vs);

#define ATTN_LOAD(s, kt) do {                                                  \
        _Pragma("unroll")                                                      \
        for (int i_ = 0; i_ < 4; i_++) {                                       \
            int idx_ = tid + i_ * 128;                                         \
            int r_ = idx_ >> 3, sg_ = idx_ & 7;                                \
            uint32_t off_ = (uint32_t)(((s) * 64 * 72 + r_ * 72 + sg_ * 8) * 2); \
            cpasync16(ksb + off_, kb + (size_t)((kt) * 64 + r_) * ldk + sg_ * 8); \
            cpasync16(vsb + off_, vb + (size_t)((kt) * 64 + r_) * ldv + sg_ * 8); \
        }                                                                      \
        asm volatile("cp.async.commit_group;" ::: "memory");                   \
    } while (0)

    ATTN_LOAD(0, 0);

#pragma unroll
    for (int i = 0; i < 4; i++) {
        int idx = tid + i * 128;
        int r = idx >> 3, sg = idx & 7;
        *(uint4*)&Qs[r * 72 + sg * 8] =
            *(const uint4*)&qb[(size_t)(q0 + r) * ldq + sg * 8];
    }
    __syncthreads();

    uint32_t aQ[4][4];
#pragma unroll
    for (int kc = 0; kc < 4; kc++) {
        uint32_t ad = smem_u32(&Qs[(warp * 16 + (lane & 15)) * 72
                                   + kc * 16 + (lane >> 4) * 8]);
        ldsm4(aQ[kc][0], aQ[kc][1], aQ[kc][2], aQ[kc][3], ad);
    }

    float m0 = -1e30f, m1 = -1e30f, l0 = 0.f, l1 = 0.f;
    float o[8][4];
#pragma unroll
    for (int j = 0; j < 8; j++)
#pragma unroll
        for (int e = 0; e < 4; e++) o[j][e] = 0.f;

    const int nkt = causal ? (q0 >> 6) + 1 : 16;
    int buf = 0;
    for (int kt = 0; kt < nkt; kt++) {
        asm volatile("cp.async.wait_group 0;" ::: "memory");
        __syncthreads();

        if (kt + 1 < nkt)
            ATTN_LOAD(buf ^ 1, kt + 1);

        float c[8][4];
#pragma unroll
        for (int j = 0; j < 8; j++)
#pragma unroll
            for (int e = 0; e < 4; e++) c[j][e] = 0.f;
#pragma unroll
        for (int kc = 0; kc < 4; kc++)
#pragma unroll
            for (int g = 0; g < 4; g++) {
                uint32_t b0, b1, b2, b3;
                uint32_t bd = smem_u32(&Ks[buf][(g * 16 + (lane & 7) + ((lane >> 4) << 3)) * 72
                                            + kc * 16 + ((lane >> 3) & 1) * 8]);
                ldsm4(b0, b1, b2, b3, bd);
                mma16816(c[2 * g], aQ[kc], b0, b1);
                mma16816(c[2 * g + 1], aQ[kc], b2, b3);
            }
#pragma unroll
        for (int j = 0; j < 8; j++)
#pragma unroll
            for (int e = 0; e < 4; e++) c[j][e] *= 0.125f;

        if (causal && kt == (q0 >> 6)) {
            int r0 = warp * 16 + (lane >> 2), r1 = r0 + 8;
#pragma unroll
            for (int j = 0; j < 8; j++) {
                int cl = 8 * j + ((lane & 3) << 1);
                if (cl     > r0) c[j][0] = -1e30f;
                if (cl + 1 > r0) c[j][1] = -1e30f;
                if (cl     > r1) c[j][2] = -1e30f;
                if (cl + 1 > r1) c[j][3] = -1e30f;
            }
        }

        float rm0 = -1e30f, rm1 = -1e30f;
#pragma unroll
        for (int j = 0; j < 8; j++) {
            rm0 = fmaxf(rm0, fmaxf(c[j][0], c[j][1]));
            rm1 = fmaxf(rm1, fmaxf(c[j][2], c[j][3]));
        }
        rm0 = fmaxf(rm0, __shfl_xor_sync(0xffffffffu, rm0, 1));
        rm0 = fmaxf(rm0, __shfl_xor_sync(0xffffffffu, rm0, 2));
        rm1 = fmaxf(rm1, __shfl_xor_sync(0xffffffffu, rm1, 1));
        rm1 = fmaxf(rm1, __shfl_xor_sync(0xffffffffu, rm1, 2));
        float mn0 = fmaxf(m0, rm0), mn1 = fmaxf(m1, rm1);
        float al0 = __expf(m0 - mn0), al1 = __expf(m1 - mn1);
        m0 = mn0; m1 = mn1;
        float rs0 = 0.f, rs1 = 0.f;
#pragma unroll
        for (int j = 0; j < 8; j++) {
            c[j][0] = __expf(c[j][0] - mn0);
            c[j][1] = __expf(c[j][1] - mn0);
            c[j][2] = __expf(c[j][2] - mn1);
            c[j][3] = __expf(c[j][3] - mn1);
            rs0 += c[j][0] + c[j][1];
            rs1 += c[j][2] + c[j][3];
        }
        rs0 += __shfl_xor_sync(0xffffffffu, rs0, 1);
        rs0 += __shfl_xor_sync(0xffffffffu, rs0, 2);
        rs1 += __shfl_xor_sync(0xffffffffu, rs1, 1);
        rs1 += __shfl_xor_sync(0xffffffffu, rs1, 2);
        l0 = l0 * al0 + rs0;
        l1 = l1 * al1 + rs1;
#pragma unroll
        for (int j = 0; j < 8; j++) {
            o[j][0] *= al0; o[j][1] *= al0;
            o[j][2] *= al1; o[j][3] *= al1;
        }

#pragma unroll
        for (int kc = 0; kc < 4; kc++) {
            uint32_t aP[4];
            aP[0] = packh2(c[2 * kc][0], c[2 * kc][1]);
            aP[1] = packh2(c[2 * kc][2], c[2 * kc][3]);
            aP[2] = packh2(c[2 * kc + 1][0], c[2 * kc + 1][1]);
            aP[3] = packh2(c[2 * kc + 1][2], c[2 * kc + 1][3]);
#pragma unroll
            for (int g = 0; g < 4; g++) {
                uint32_t b0, b1, b2, b3;
                uint32_t bd = smem_u32(&Vs[buf][(kc * 16 + (lane & 15)) * 72
                                            + g * 16 + (lane >> 4) * 8]);
                ldsm4t(b0, b1, b2, b3, bd);
                mma16816(o[2 * g], aP, b0, b1);
                mma16816(o[2 * g + 1], aP, b2, b3);
            }
        }
        buf ^= 1;
    }
#undef ATTN_LOAD

    float i0 = 1.f / l0, i1 = 1.f / l1;
    const int r0 = q0 + warp * 16 + (lane >> 2);
    size_t ro0 = (size_t)(b * SN + r0) * 1024 + h * 64;
    size_t ro1 = ro0 + (size_t)8 * 1024;
#pragma unroll
    for (int j = 0; j < 8; j++) {
        int cl = 8 * j + ((lane & 3) << 1);
        *(__half2*)&Op[ro0 + cl] = __floats2half2_rn(o[j][0] * i0, o[j][1] * i0);
        *(__half2*)&Op[ro1 + cl] = __floats2half2_rn(o[j][2] * i1, o[j][3] * i1);
    }
}

// ---------------------------------------------------------------------------
// LayerNorm; optional plain fp16 side-output (pitch 1024)
// ---------------------------------------------------------------------------
__global__ __launch_bounds__(256)
void ln_k(const float* __restrict__ X, const float* __restrict__ g,
          const float* __restrict__ be, float* __restrict__ Y,
          __half* __restrict__ S) {
    const int row = blockIdx.x;
    const int tid = threadIdx.x;
    const unsigned lane = tid & 31, warp = tid >> 5;

    __shared__ float red[8];
    __shared__ float stat[2];

    float4 v = *(const float4*)&X[(size_t)row * 1024 + tid * 4];
    float s = v.x + v.y + v.z + v.w;
#pragma unroll
    for (int off = 16; off; off >>= 1) s += __shfl_xor_sync(0xffffffffu, s, off);
    if (lane == 0) red[warp] = s;
    __syncthreads();
    if (tid == 0) {
        float t = 0.f;
#pragma unroll
        for (int i = 0; i < 8; i++) t += red[i];
        stat[0] = t * (1.f / 1024.f);
    }
    __syncthreads();
    const float mean = stat[0];
    float dx = v.x - mean, dy = v.y - mean, dz = v.z - mean, dw = v.w - mean;
    float sq = dx * dx + dy * dy + dz * dz + dw * dw;
#pragma unroll
    for (int off = 16; off; off >>= 1) sq += __shfl_xor_sync(0xffffffffu, sq, off);
    if (lane == 0) red[warp] = sq;
    __syncthreads();
    if (tid == 0) {
        float t = 0.f;
#pragma unroll
        for (int i = 0; i < 8; i++) t += red[i];
        stat[1] = rsqrtf(t * (1.f / 1024.f) + 1e-5f);
    }
    __syncthreads();
    const float rstd = stat[1];
    const int c = tid * 4;
    float4 gv = *(const float4*)&g[c];
    float4 bv = *(const float4*)&be[c];
    float4 r;
    r.x = gv.x * dx * rstd + bv.x;
    r.y = gv.y * dy * rstd + bv.y;
    r.z = gv.z * dz * rstd + bv.z;
    r.w = gv.w * dw * rstd + bv.w;
    *(float4*)&Y[(size_t)row * 1024 + c] = r;
    if (S) {
        __half2 H0 = __floats2half2_rn(r.x, r.y);
        __half2 H1 = __floats2half2_rn(r.z, r.w);
        uint2 hu;
        hu.x = *(unsigned*)&H0; hu.y = *(unsigned*)&H1;
        *(uint2*)&S[(size_t)row * 1024 + c] = hu;
    }
}

// ---------------------------------------------------------------------------
// Launcher: 2-way M-parallel execution + fork/join streams
// ---------------------------------------------------------------------------
extern "C" void kernel_launch(void* const* d_in, const int* in_sizes, int n_in,
                              void* d_out, int out_size) {
    const float* x    = (const float*)d_in[0];
    const float* enc  = (const float*)d_in[2];
    const float* Wq1  = (const float*)d_in[4];
    const float* bq1  = (const float*)d_in[5];
    const float* Wk1  = (const float*)d_in[6];
    const float* bk1  = (const float*)d_in[7];
    const float* Wv1  = (const float*)d_in[8];
    const float* bv1  = (const float*)d_in[9];
    const float* Wo1  = (const float*)d_in[10];
    const float* bo1  = (const float*)d_in[11];
    const float* Wq2  = (const float*)d_in[12];
    const float* bq2  = (const float*)d_in[13];
    const float* Wk2  = (const float*)d_in[14];
    const float* bk2  = (const float*)d_in[15];
    const float* Wv2  = (const float*)d_in[16];
    const float* bv2  = (const float*)d_in[17];
    const float* Wo2  = (const float*)d_in[18];
    const float* bo2  = (const float*)d_in[19];
    const float* W1f  = (const float*)d_in[20];
    const float* b1f  = (const float*)d_in[21];
    const float* W2f  = (const float*)d_in[22];
    const float* b2f  = (const float*)d_in[23];
    const float* g1   = (const float*)d_in[24];
    const float* be1  = (const float*)d_in[25];
    const float* g2   = (const float*)d_in[26];
    const float* be2  = (const float*)d_in[27];
    const float* g3   = (const float*)d_in[28];
    const float* be3  = (const float*)d_in[29];
    float* out = (float*)d_out;

    float *tbuf, *x1, *x2, *hbuf;
    __half *qkv1h, *q2h, *kv2h, *abuf, *ench;
    __half *wqkv1p, *wo1p, *wq2p, *wkv2p, *wo2p, *w1fp, *w2fp;
    cudaGetSymbolAddress((void**)&tbuf,   g_t);
    cudaGetSymbolAddress((void**)&x1,     g_x1);
    cudaGetSymbolAddress((void**)&x2,     g_x2);
    cudaGetSymbolAddress((void**)&hbuf,   g_h);
    cudaGetSymbolAddress((void**)&qkv1h,  g_qkv1h);
    cudaGetSymbolAddress((void**)&q2h,    g_q2h);
    cudaGetSymbolAddress((void**)&kv2h,   g_kv2h);
    cudaGetSymbolAddress((void**)&abuf,   g_abuf);
    cudaGetSymbolAddress((void**)&ench,   g_ench);
    cudaGetSymbolAddress((void**)&wqkv1p, g_wqkv1p);
    cudaGetSymbolAddress((void**)&wo1p,   g_wo1p);
    cudaGetSymbolAddress((void**)&wq2p,   g_wq2p);
    cudaGetSymbolAddress((void**)&wkv2p,  g_wkv2p);
    cudaGetSymbolAddress((void**)&wo2p,   g_wo2p);
    cudaGetSymbolAddress((void**)&w1fp,   g_w1fp);
    cudaGetSymbolAddress((void**)&w2fp,   g_w2fp);

    __half* hidden = (__half*)hbuf;   // [MTOK][4096] fp16

    cudaFuncSetAttribute(gemm_mma<false, false, 1, true>,
                         cudaFuncAttributeMaxDynamicSharedMemorySize, GSMEM);
    cudaFuncSetAttribute(gemm_mma<false, false, 1, false>,
                         cudaFuncAttributeMaxDynamicSharedMemorySize, GSMEM);
    cudaFuncSetAttribute(gemm_mma<false, true, 0, false>,
                         cudaFuncAttributeMaxDynamicSharedMemorySize, GSMEM);
    cudaFuncSetAttribute(gemm_mma<true, false, 1, false>,
                         cudaFuncAttributeMaxDynamicSharedMemorySize, GSMEM);

    // ---- Weight conversion jobs (shared) ----
    WJobs jobs;
    auto mk = [](const float* X, __half* Y, int K, int Nin, int rowOff,
                 long hStride, int heads) {
        WJob j;
        j.X = X; j.Y = Y; j.K = K; j.Nin = Nin; j.rowOff = rowOff;
        j.tilesX = Nin / 32;
        j.tilesPerHead = (Nin / 32) * (K / 32);
        j.count = j.tilesPerHead * heads;
        j.hStride = hStride;
        return j;
    };
    jobs.j[0] = mk(Wq1, wqkv1p, 1024, 64, 0,    65536, 16);
    jobs.j[1] = mk(Wk1, wqkv1p, 1024, 64, 1024, 65536, 16);
    jobs.j[2] = mk(Wv1, wqkv1p, 1024, 64, 2048, 65536, 16);
    jobs.j[3] = mk(Wo1, wo1p,  1024, 1024, 0, 0, 1);
    jobs.j[4] = mk(Wq2, wq2p,  1024, 64, 0,    65536, 16);
    jobs.j[5] = mk(Wk2, wkv2p, 1024, 64, 0,    65536, 16);
    jobs.j[6] = mk(Wv2, wkv2p, 1024, 64, 1024, 65536, 16);
    jobs.j[7] = mk(Wo2, wo2p,  1024, 1024, 0, 0, 1);
    jobs.j[8] = mk(W1f, w1fp,  1024, 4096, 0, 0, 1);
    jobs.j[9] = mk(W2f, w2fp,  4096, 1024, 0, 0, 1);
    int total = 0;
    for (int i = 0; i < 10; i++) total += jobs.j[i].count;

    cudaStream_t s1;
    cudaStreamCreateWithFlags(&s1, cudaStreamNonBlocking);
    cudaEvent_t evFork, evJoin;
    cudaEventCreateWithFlags(&evFork, cudaEventDisableTiming);
    cudaEventCreateWithFlags(&evJoin, cudaEventDisableTiming);

    convw<<<total, 256>>>(jobs);
    cudaEventRecord(evFork, 0);
    cudaStreamWaitEvent(s1, evFork, 0);

    // One half-chain (2048 rows = 2 batches), stream-parametrized
    auto half_chain = [&](int r0, cudaStream_t st) {
        const size_t o1 = (size_t)r0 * 1024;
        const size_t o2 = (size_t)r0 * 2048;
        const size_t o3 = (size_t)r0 * 3072;
        const size_t o4 = (size_t)r0 * 4096;

        converta<<<1024, 256, 0, st>>>(x + o1, abuf + o1);
        converta<<<1024, 256, 0, st>>>(enc + o1, ench + o1);

        // QKV projection (half): M=2048 -> 16 blocks, N=3072 -> 48
        gemm_mma<false, false, 1, true><<<dim3(16, 48), 256, GSMEM, st>>>(
            abuf + o1, wqkv1p, bq1, bk1, bv1, nullptr, nullptr,
            qkv1h + o3, 3072, 1024, 3072);
        // KV2: N=2048 -> 32
        gemm_mma<false, false, 1, true><<<dim3(16, 32), 256, GSMEM, st>>>(
            ench + o1, wkv2p, bk2, bv2, bv2, nullptr, nullptr,
            kv2h + o2, 2048, 1024, 2048);

        // Self-attention (2 batches -> grid.y = 32)
        attn_h<<<dim3(16, 32), 128, 0, st>>>(
            qkv1h + o3, 3072, qkv1h + o3 + 1024, 3072,
            qkv1h + o3 + 2048, 3072, abuf + o1, 1);
        gemm_mma<false, true, 0, false><<<dim3(16, 16), 256, GSMEM, st>>>(
            abuf + o1, wo1p, bo1, nullptr, nullptr, x + o1,
            tbuf + o1, nullptr, 1024, 1024, 0);
        ln_k<<<2048, 256, 0, st>>>(tbuf + o1, g1, be1, x1 + o1, abuf + o1);

        // Cross-attention
        gemm_mma<false, false, 1, false><<<dim3(16, 16), 256, GSMEM, st>>>(
            abuf + o1, wq2p, bq2, nullptr, nullptr, nullptr, nullptr,
            q2h + o1, 1024, 1024, 1024);
        attn_h<<<dim3(16, 32), 128, 0, st>>>(
            q2h + o1, 1024, kv2h + o2, 2048,
            kv2h + o2 + 1024, 2048, abuf + o1, 0);
        gemm_mma<false, true, 0, false><<<dim3(16, 16), 256, GSMEM, st>>>(
            abuf + o1, wo2p, bo2, nullptr, nullptr, x1 + o1,
            tbuf + o1, nullptr, 1024, 1024, 0);
        ln_k<<<2048, 256, 0, st>>>(tbuf + o1, g2, be2, x2 + o1, abuf + o1);

        // FFN: N=4096 -> 64
        gemm_mma<true, false, 1, false><<<dim3(16, 64), 256, GSMEM, st>>>(
            abuf + o1, w1fp, b1f, nullptr, nullptr, nullptr, nullptr,
            hidden + o4, 4096, 1024, 4096);
        gemm_mma<false, true, 0, false><<<dim3(16, 16), 256, GSMEM, st>>>(
            hidden + o4, w2fp, b2f, nullptr, nullptr, x2 + o1,
            tbuf + o1, nullptr, 1024, 4096, 0);
        ln_k<<<2048, 256, 0, st>>>(tbuf + o1, g3, be3, out + o1, nullptr);
    };

    half_chain(0, (cudaStream_t)0);
    half_chain(2048, s1);

    cudaEventRecord(evJoin, s1);
    cudaStreamWaitEvent(0, evJoin, 0);
}

// round 14
// speedup vs baseline: 1.1574x; 1.1574x over previous
#include <cuda_runtime.h>
#include <cuda_fp16.h>
#include <cstdint>

// Problem constants
#define BN   4
#define SN   1024
#define MTOK (BN * SN)   // 4096

// ---------------------------------------------------------------------------
// Device scratch
// ---------------------------------------------------------------------------
__device__ float g_t    [MTOK * 1024];
__device__ float g_x1   [MTOK * 1024];
__device__ float g_x2   [MTOK * 1024];
__device__ float g_h    [MTOK * 4096];   // reused as half[MTOK*4096] (hidden)

__device__ __half g_qkv1h[MTOK * 3072];
__device__ __half g_q2h  [MTOK * 1024];
__device__ __half g_kv2h [MTOK * 2048];
__device__ __half g_abuf [MTOK * 1024];
__device__ __half g_ench [MTOK * 1024];

// fp16 weights (transposed to [N x K] row-major)
__device__ __half g_wqkv1p[3072 * 1024];
__device__ __half g_wo1p  [1024 * 1024];
__device__ __half g_wq2p  [1024 * 1024];
__device__ __half g_wkv2p [2048 * 1024];
__device__ __half g_wo2p  [1024 * 1024];
__device__ __half g_w1fp  [4096 * 1024];
__device__ __half g_w2fp  [1024 * 4096];

// ---------------------------------------------------------------------------
// PTX helpers
// ---------------------------------------------------------------------------
__device__ __forceinline__ uint32_t smem_u32(const void* p) {
    uint32_t a;
    asm("{ .reg .u64 t; cvta.to.shared.u64 t, %1; cvt.u32.u64 %0, t; }"
        : "=r"(a) : "l"(p));
    return a;
}

__device__ __forceinline__ void cpasync16(uint32_t dst, const void* src) {
    asm volatile("cp.async.cg.shared.global [%0], [%1], 16;"
                 :: "r"(dst), "l"(src));
}

__device__ __forceinline__ void ldsm4(uint32_t& r0, uint32_t& r1,
                                      uint32_t& r2, uint32_t& r3, uint32_t a) {
    asm volatile("ldmatrix.sync.aligned.m8n8.x4.shared.b16 {%0,%1,%2,%3}, [%4];"
                 : "=r"(r0), "=r"(r1), "=r"(r2), "=r"(r3) : "r"(a));
}

__device__ __forceinline__ void ldsm4t(uint32_t& r0, uint32_t& r1,
                                       uint32_t& r2, uint32_t& r3, uint32_t a) {
    asm volatile("ldmatrix.sync.aligned.m8n8.x4.trans.shared.b16 {%0,%1,%2,%3}, [%4];"
                 : "=r"(r0), "=r"(r1), "=r"(r2), "=r"(r3) : "r"(a));
}

__device__ __forceinline__ void mma16816(float* c, const uint32_t* a,
                                         uint32_t b0, uint32_t b1) {
    asm volatile(
        "mma.sync.aligned.m16n8k16.row.col.f32.f16.f16.f32 "
        "{%0,%1,%2,%3}, {%4,%5,%6,%7}, {%8,%9}, {%0,%1,%2,%3};"
        : "+f"(c[0]), "+f"(c[1]), "+f"(c[2]), "+f"(c[3])
        : "r"(a[0]), "r"(a[1]), "r"(a[2]), "r"(a[3]), "r"(b0), "r"(b1));
}

__device__ __forceinline__ uint32_t packh2(float a, float b) {
    __half2 h = __floats2half2_rn(a, b);
    return *(uint32_t*)&h;
}

// ---------------------------------------------------------------------------
// Batched weight transpose+convert: 10 jobs in ONE launch.
// ---------------------------------------------------------------------------
struct WJob {
    const float* X; __half* Y;
    int K, Nin, rowOff, tilesX, tilesPerHead, count;
    long hStride;
};
struct WJobs { WJob j[10]; };

__global__ __launch_bounds__(256)
void convw(WJobs jobs) {
    int t = blockIdx.x;
    int i = 0;
    while (i < 9 && t >= jobs.j[i].count) { t -= jobs.j[i].count; i++; }
    const WJob jb = jobs.j[i];
    const int h = t / jb.tilesPerHead;
    const int rem = t % jb.tilesPerHead;
    const int ky = rem / jb.tilesX, nx = rem % jb.tilesX;
    const float* X = jb.X + (long)h * jb.hStride;
    const int rowOff = jb.rowOff + h * jb.Nin;
    const int n0 = nx * 32, k0 = ky * 32;

    __shared__ float tl[32][33];
    const int tx = threadIdx.x & 31, ty = threadIdx.x >> 5;
#pragma unroll
    for (int r = 0; r < 4; r++)
        tl[ty + 8 * r][tx] = X[(long)(k0 + ty + 8 * r) * jb.Nin + n0 + tx];
    __syncthreads();
#pragma unroll
    for (int r = 0; r < 4; r++) {
        const int n = n0 + ty + 8 * r, k = k0 + tx;
        jb.Y[(long)(rowOff + n) * jb.K + k] = __float2half_rn(tl[tx][ty + 8 * r]);
    }
}

// ---------------------------------------------------------------------------
// Convert activations: X fp32 [n] -> Y fp16 [n]
// ---------------------------------------------------------------------------
__global__ __launch_bounds__(256)
void converta(const float* __restrict__ X, __half* __restrict__ Y) {
    const size_t i = ((size_t)blockIdx.x * 256 + threadIdx.x) << 3;
    float4 a = *(const float4*)&X[i];
    float4 b = *(const float4*)&X[i + 4];
    __half2 h0 = __floats2half2_rn(a.x, a.y);
    __half2 h1 = __floats2half2_rn(a.z, a.w);
    __half2 h2 = __floats2half2_rn(b.x, b.y);
    __half2 h3 = __floats2half2_rn(b.z, b.w);
    uint4 u;
    u.x = *(unsigned*)&h0; u.y = *(unsigned*)&h1;
    u.z = *(unsigned*)&h2; u.w = *(unsigned*)&h3;
    *(uint4*)&Y[i] = u;
}

// ---------------------------------------------------------------------------
// HMMA fp16 GEMM (round-12 proven optimum): CTA 128x128, warptile 64x32,
// K-step 64, 3-stage cp.async, 2 CTAs/SM.
// ---------------------------------------------------------------------------
#define SMP 72
#define STGH (128 * SMP)
#define GSMEM (3 * 2 * STGH * 2)   // 110592 B

template<bool RELU, bool RES, int OUT, bool SEG>
__global__ __launch_bounds__(256, 2)
void gemm_mma(const __half* __restrict__ A, const __half* __restrict__ Bw,
              const float* __restrict__ b0, const float* __restrict__ b1v,
              const float* __restrict__ b2, const float* __restrict__ R,
              float* __restrict__ C32, __half* __restrict__ C16,
              int N, int Kp, int P2) {
    extern __shared__ __half smh[];
    __half* As = smh;
    __half* Bs = smh + 3 * STGH;

    const int tid = threadIdx.x, lane = tid & 31, warp = tid >> 5;
    const int m0 = blockIdx.x * 128, n0 = blockIdx.y * 128;
    const int wm = (warp & 1) * 64, wn = (warp >> 1) * 32;

    const uint32_t asb = smem_u32(As);
    const uint32_t bsb = smem_u32(Bs);
    const __half* Ab = A + (size_t)m0 * Kp;
    const __half* Bb = Bw + (size_t)n0 * Kp;

    float acc[4][4][4];
#pragma unroll
    for (int i = 0; i < 4; i++)
#pragma unroll
        for (int j = 0; j < 4; j++)
#pragma unroll
            for (int k = 0; k < 4; k++) acc[i][j][k] = 0.f;

#define LOAD_STAGE(s, k0) do {                                                  \
        _Pragma("unroll")                                                       \
        for (int i_ = 0; i_ < 4; i_++) {                                        \
            int idx_ = tid + (i_ << 8);                                         \
            int rr_ = idx_ >> 3, sg_ = idx_ & 7;                                \
            uint32_t so_ = (uint32_t)(((s) * STGH + rr_ * SMP + sg_ * 8) * 2);  \
            size_t go_ = (size_t)rr_ * Kp + (size_t)(k0) + sg_ * 8;             \
            cpasync16(asb + so_, Ab + go_);                                     \
            cpasync16(bsb + so_, Bb + go_);                                     \
        }                                                                       \
        asm volatile("cp.async.commit_group;" ::: "memory");                    \
    } while (0)

    const int nst = Kp >> 6;
    LOAD_STAGE(0, 0);
    LOAD_STAGE(1, 64);

    int s = 0, sn = 2;
    for (int kt = 0; kt < nst; kt++) {
        if (kt + 1 < nst)
            asm volatile("cp.async.wait_group 1;" ::: "memory");
        else
            asm volatile("cp.async.wait_group 0;" ::: "memory");
        __syncthreads();

        if (kt + 2 < nst) {
            LOAD_STAGE(sn, (kt + 2) << 6);
            sn = (sn == 2) ? 0 : sn + 1;
        }

        const uint32_t sA = asb + (uint32_t)(s * STGH * 2);
        const uint32_t sB = bsb + (uint32_t)(s * STGH * 2);
        s = (s == 2) ? 0 : s + 1;

#pragma unroll
        for (int kk = 0; kk < 4; kk++) {
            uint32_t aF[4][4], bF[2][4];
#pragma unroll
            for (int mt = 0; mt < 4; mt++) {
                uint32_t ad = sA + (uint32_t)(((wm + mt * 16 + (lane & 15)) * SMP
                                  + kk * 16 + (lane >> 4) * 8) * 2);
                ldsm4(aF[mt][0], aF[mt][1], aF[mt][2], aF[mt][3], ad);
            }
#pragma unroll
            for (int g = 0; g < 2; g++) {
                int nr = wn + g * 16 + (lane & 7) + ((lane >> 4) << 3);
                int kc = kk * 16 + ((lane >> 3) & 1) * 8;
                uint32_t bd = sB + (uint32_t)((nr * SMP + kc) * 2);
                ldsm4(bF[g][0], bF[g][1], bF[g][2], bF[g][3], bd);
            }
#pragma unroll
            for (int mt = 0; mt < 4; mt++)
#pragma unroll
                for (int nt = 0; nt < 4; nt++)
                    mma16816(acc[mt][nt], aF[mt],
                             bF[nt >> 1][(nt & 1) * 2],
                             bF[nt >> 1][(nt & 1) * 2 + 1]);
        }
    }
#undef LOAD_STAGE

    const float* bias = b0;
    int cb0 = n0;
    if (SEG) {
        const int sg = n0 >> 10;
        bias = (sg == 0) ? b0 : ((sg == 1) ? b1v : b2);
        cb0 = n0 & 1023;
    }

#pragma unroll
    for (int mt = 0; mt < 4; mt++) {
        const int r0 = m0 + wm + mt * 16 + (lane >> 2);
#pragma unroll
        for (int nt = 0; nt < 4; nt++) {
            const int cl = wn + nt * 8 + ((lane & 3) << 1);
            const int c = n0 + cl;
            float2 bv = *(const float2*)&bias[cb0 + cl];
            float2 v0, v1;
            v0.x = acc[mt][nt][0] + bv.x; v0.y = acc[mt][nt][1] + bv.y;
            v1.x = acc[mt][nt][2] + bv.x; v1.y = acc[mt][nt][3] + bv.y;
            if (RES) {
                float2 ra = *(const float2*)&R[(size_t)r0 * N + c];
                float2 rb = *(const float2*)&R[(size_t)(r0 + 8) * N + c];
                v0.x += ra.x; v0.y += ra.y;
                v1.x += rb.x; v1.y += rb.y;
            }
            if (RELU) {
                v0.x = fmaxf(v0.x, 0.f); v0.y = fmaxf(v0.y, 0.f);
                v1.x = fmaxf(v1.x, 0.f); v1.y = fmaxf(v1.y, 0.f);
            }
            if (OUT == 0) {
                *(float2*)&C32[(size_t)r0 * N + c] = v0;
                *(float2*)&C32[(size_t)(r0 + 8) * N + c] = v1;
            } else {
                __half2 h0 = __floats2half2_rn(v0.x, v0.y);
                __half2 h1 = __floats2half2_rn(v1.x, v1.y);
                *(__half2*)&C16[(size_t)r0 * P2 + c] = h0;
                *(__half2*)&C16[(size_t)(r0 + 8) * P2 + c] = h1;
            }
        }
    }
}

// ---------------------------------------------------------------------------
// HMMA fp16 flash attention v2: 128 queries/block, 256 threads (8 warps),
// double-buffered cp.async K/V. K/V global traffic halved vs 64-row tiles.
// Dynamic SMEM: Qs[128*72] | Ks[2][64*72] | Vs[2][64*72] = 55296 B.
// ---------------------------------------------------------------------------
#define ASMEM ((128 + 4 * 64) * 72 * 2)

__global__ __launch_bounds__(256)
void attn_h(const __half* __restrict__ Qp, int ldq,
            const __half* __restrict__ Kp, int ldk,
            const __half* __restrict__ Vp, int ldv,
            __half* __restrict__ Op, int causal) {
    extern __shared__ __half asm_[];
    __half* Qs = asm_;                       // [128*72]
    __half* Ks = asm_ + 128 * 72;            // [2][64*72]
    __half* Vs = asm_ + (128 + 2 * 64) * 72; // [2][64*72]

    const int tid = threadIdx.x, lane = tid & 31, warp = tid >> 5;
    const int q0 = blockIdx.x * 128;
    const int b = blockIdx.y >> 4, h = blockIdx.y & 15;

    const __half* qb = Qp + (size_t)(b * SN) * ldq + h * 64;
    const __half* kb = Kp + (size_t)(b * SN) * ldk + h * 64;
    const __half* vb = Vp + (size_t)(b * SN) * ldv + h * 64;

    const uint32_t ksb = smem_u32(Ks);
    const uint32_t vsb = smem_u32(Vs);

#define ATTN_LOAD(s, kt) do {                                                  \
        _Pragma("unroll")                                                      \
        for (int i_ = 0; i_ < 2; i_++) {                                       \
            int idx_ = tid + i_ * 256;                                         \
            int r_ = idx_ >> 3, sg_ = idx_ & 7;                                \
            uint32_t off_ = (uint32_t)(((s) * 64 * 72 + r_ * 72 + sg_ * 8) * 2); \
            cpasync16(ksb + off_, kb + (size_t)((kt) * 64 + r_) * ldk + sg_ * 8); \
            cpasync16(vsb + off_, vb + (size_t)((kt) * 64 + r_) * ldv + sg_ * 8); \
        }                                                                      \
        asm volatile("cp.async.commit_group;" ::: "memory");                   \
    } while (0)

    ATTN_LOAD(0, 0);

    // Load Q tile (128 x 64 halfs)
#pragma unroll
    for (int i = 0; i < 4; i++) {
        int idx = tid + i * 256;
        int r = idx >> 3, sg = idx & 7;
        *(uint4*)&Qs[r * 72 + sg * 8] =
            *(const uint4*)&qb[(size_t)(q0 + r) * ldq + sg * 8];
    }
    __syncthreads();

    uint32_t aQ[4][4];
#pragma unroll
    for (int kc = 0; kc < 4; kc++) {
        uint32_t ad = smem_u32(&Qs[(warp * 16 + (lane & 15)) * 72
                                   + kc * 16 + (lane >> 4) * 8]);
        ldsm4(aQ[kc][0], aQ[kc][1], aQ[kc][2], aQ[kc][3], ad);
    }

    float m0 = -1e30f, m1 = -1e30f, l0 = 0.f, l1 = 0.f;
    float o[8][4];
#pragma unroll
    for (int j = 0; j < 8; j++)
#pragma unroll
        for (int e = 0; e < 4; e++) o[j][e] = 0.f;

    const int nkt = causal ? (q0 >> 6) + 2 : 16;
    const int grow0 = q0 + warp * 16 + (lane >> 2);   // this thread's row (first)
    int buf = 0;
    for (int kt = 0; kt < nkt; kt++) {
        asm volatile("cp.async.wait_group 0;" ::: "memory");
        __syncthreads();

        if (kt + 1 < nkt)
            ATTN_LOAD(buf ^ 1, kt + 1);

        float c[8][4];
#pragma unroll
        for (int j = 0; j < 8; j++)
#pragma unroll
            for (int e = 0; e < 4; e++) c[j][e] = 0.f;
#pragma unroll
        for (int kc = 0; kc < 4; kc++)
#pragma unroll
            for (int g = 0; g < 4; g++) {
                uint32_t b0, b1, b2, b3;
                uint32_t bd = smem_u32(&Ks[buf * 64 * 72
                                   + (g * 16 + (lane & 7) + ((lane >> 4) << 3)) * 72
                                   + kc * 16 + ((lane >> 3) & 1) * 8]);
                ldsm4(b0, b1, b2, b3, bd);
                mma16816(c[2 * g], aQ[kc], b0, b1);
                mma16816(c[2 * g + 1], aQ[kc], b2, b3);
            }
#pragma unroll
        for (int j = 0; j < 8; j++)
#pragma unroll
            for (int e = 0; e < 4; e++) c[j][e] *= 0.125f;

        // Causal mask (global row/col compare) on the last two k-tiles
        if (causal && kt * 64 + 63 > grow0 - 8) {
            const int r0g = grow0, r1g = grow0 + 8;
#pragma unroll
            for (int j = 0; j < 8; j++) {
                int gc = kt * 64 + 8 * j + ((lane & 3) << 1);
                if (gc     > r0g) c[j][0] = -1e30f;
                if (gc + 1 > r0g) c[j][1] = -1e30f;
                if (gc     > r1g) c[j][2] = -1e30f;
                if (gc + 1 > r1g) c[j][3] = -1e30f;
            }
        }

        float rm0 = -1e30f, rm1 = -1e30f;
#pragma unroll
        for (int j = 0; j < 8; j++) {
            rm0 = fmaxf(rm0, fmaxf(c[j][0], c[j][1]));
            rm1 = fmaxf(rm1, fmaxf(c[j][2], c[j][3]));
        }
        rm0 = fmaxf(rm0, __shfl_xor_sync(0xffffffffu, rm0, 1));
        rm0 = fmaxf(rm0, __shfl_xor_sync(0xffffffffu, rm0, 2));
        rm1 = fmaxf(rm1, __shfl_xor_sync(0xffffffffu, rm1, 1));
        rm1 = fmaxf(rm1, __shfl_xor_sync(0xffffffffu, rm1, 2));
        float mn0 = fmaxf(m0, rm0), mn1 = fmaxf(m1, rm1);
        float al0 = __expf(m0 - mn0), al1 = __expf(m1 - mn1);
        m0 = mn0; m1 = mn1;
        float rs0 = 0.f, rs1 = 0.f;
#pragma unroll
        for (int j = 0; j < 8; j++) {
            c[j][0] = __expf(c[j][0] - mn0);
            c[j][1] = __expf(c[j][1] - mn0);
            c[j][2] = __expf(c[j][2] - mn1);
            c[j][3] = __expf(c[j][3] - mn1);
            rs0 += c[j][0] + c[j][1];
            rs1 += c[j][2] + c[j][3];
        }
        rs0 += __shfl_xor_sync(0xffffffffu, rs0, 1);
        rs0 += __shfl_xor_sync(0xffffffffu, rs0, 2);
        rs1 += __shfl_xor_sync(0xffffffffu, rs1, 1);
        rs1 += __shfl_xor_sync(0xffffffffu, rs1, 2);
        l0 = l0 * al0 + rs0;
        l1 = l1 * al1 + rs1;
#pragma unroll
        for (int j = 0; j < 8; j++) {
            o[j][0] *= al0; o[j][1] *= al0;
            o[j][2] *= al1; o[j][3] *= al1;
        }

#pragma unroll
        for (int kc = 0; kc < 4; kc++) {
            uint32_t aP[4];
            aP[0] = packh2(c[2 * kc][0], c[2 * kc][1]);
            aP[1] = packh2(c[2 * kc][2], c[2 * kc][3]);
            aP[2] = packh2(c[2 * kc + 1][0], c[2 * kc + 1][1]);
            aP[3] = packh2(c[2 * kc + 1][2], c[2 * kc + 1][3]);
#pragma unroll
            for (int g = 0; g < 4; g++) {
                uint32_t b0, b1, b2, b3;
                uint32_t bd = smem_u32(&Vs[buf * 64 * 72
                                   + (kc * 16 + (lane & 15)) * 72
                                   + g * 16 + (lane >> 4) * 8]);
                ldsm4t(b0, b1, b2, b3, bd);
                mma16816(o[2 * g], aP, b0, b1);
                mma16816(o[2 * g + 1], aP, b2, b3);
            }
        }
        buf ^= 1;
    }
#undef ATTN_LOAD

    float i0 = 1.f / l0, i1 = 1.f / l1;
    const int r0 = q0 + warp * 16 + (lane >> 2);
    size_t ro0 = (size_t)(b * SN + r0) * 1024 + h * 64;
    size_t ro1 = ro0 + (size_t)8 * 1024;
#pragma unroll
    for (int j = 0; j < 8; j++) {
        int cl = 8 * j + ((lane & 3) << 1);
        *(__half2*)&Op[ro0 + cl] = __floats2half2_rn(o[j][0] * i0, o[j][1] * i0);
        *(__half2*)&Op[ro1 + cl] = __floats2half2_rn(o[j][2] * i1, o[j][3] * i1);
    }
}

// ---------------------------------------------------------------------------
// LayerNorm; optional plain fp16 side-output (pitch 1024)
// ---------------------------------------------------------------------------
__global__ __launch_bounds__(256)
void ln_k(const float* __restrict__ X, const float* __restrict__ g,
          const float* __restrict__ be, float* __restrict__ Y,
          __half* __restrict__ S) {
    const int row = blockIdx.x;
    const int tid = threadIdx.x;
    const unsigned lane = tid & 31, warp = tid >> 5;

    __shared__ float red[8];
    __shared__ float stat[2];

    float4 v = *(const float4*)&X[(size_t)row * 1024 + tid * 4];
    float s = v.x + v.y + v.z + v.w;
#pragma unroll
    for (int off = 16; off; off >>= 1) s += __shfl_xor_sync(0xffffffffu, s, off);
    if (lane == 0) red[warp] = s;
    __syncthreads();
    if (tid == 0) {
        float t = 0.f;
#pragma unroll
        for (int i = 0; i < 8; i++) t += red[i];
        stat[0] = t * (1.f / 1024.f);
    }
    __syncthreads();
    const float mean = stat[0];
    float dx = v.x - mean, dy = v.y - mean, dz = v.z - mean, dw = v.w - mean;
    float sq = dx * dx + dy * dy + dz * dz + dw * dw;
#pragma unroll
    for (int off = 16; off; off >>= 1) sq += __shfl_xor_sync(0xffffffffu, sq, off);
    if (lane == 0) red[warp] = sq;
    __syncthreads();
    if (tid == 0) {
        float t = 0.f;
#pragma unroll
        for (int i = 0; i < 8; i++) t += red[i];
        stat[1] = rsqrtf(t * (1.f / 1024.f) + 1e-5f);
    }
    __syncthreads();
    const float rstd = stat[1];
    const int c = tid * 4;
    float4 gv = *(const float4*)&g[c];
    float4 bv = *(const float4*)&be[c];
    float4 r;
    r.x = gv.x * dx * rstd + bv.x;
    r.y = gv.y * dy * rstd + bv.y;
    r.z = gv.z * dz * rstd + bv.z;
    r.w = gv.w * dw * rstd + bv.w;
    *(float4*)&Y[(size_t)row * 1024 + c] = r;
    if (S) {
        __half2 H0 = __floats2half2_rn(r.x, r.y);
        __half2 H1 = __floats2half2_rn(r.z, r.w);
        uint2 hu;
        hu.x = *(unsigned*)&H0; hu.y = *(unsigned*)&H1;
        *(uint2*)&S[(size_t)row * 1024 + c] = hu;
    }
}

// ---------------------------------------------------------------------------
// Launcher: 2-way M-parallel execution + fork/join streams
// ---------------------------------------------------------------------------
extern "C" void kernel_launch(void* const* d_in, const int* in_sizes, int n_in,
                              void* d_out, int out_size) {
    const float* x    = (const float*)d_in[0];
    const float* enc  = (const float*)d_in[2];
    const float* Wq1  = (const float*)d_in[4];
    const float* bq1  = (const float*)d_in[5];
    const float* Wk1  = (const float*)d_in[6];
    const float* bk1  = (const float*)d_in[7];
    const float* Wv1  = (const float*)d_in[8];
    const float* bv1  = (const float*)d_in[9];
    const float* Wo1  = (const float*)d_in[10];
    const float* bo1  = (const float*)d_in[11];
    const float* Wq2  = (const float*)d_in[12];
    const float* bq2  = (const float*)d_in[13];
    const float* Wk2  = (const float*)d_in[14];
    const float* bk2  = (const float*)d_in[15];
    const float* Wv2  = (const float*)d_in[16];
    const float* bv2  = (const float*)d_in[17];
    const float* Wo2  = (const float*)d_in[18];
    const float* bo2  = (const float*)d_in[19];
    const float* W1f  = (const float*)d_in[20];
    const float* b1f  = (const float*)d_in[21];
    const float* W2f  = (const float*)d_in[22];
    const float* b2f  = (const float*)d_in[23];
    const float* g1   = (const float*)d_in[24];
    const float* be1  = (const float*)d_in[25];
    const float* g2   = (const float*)d_in[26];
    const float* be2  = (const float*)d_in[27];
    const float* g3   = (const float*)d_in[28];
    const float* be3  = (const float*)d_in[29];
    float* out = (float*)d_out;

    float *tbuf, *x1, *x2, *hbuf;
    __half *qkv1h, *q2h, *kv2h, *abuf, *ench;
    __half *wqkv1p, *wo1p, *wq2p, *wkv2p, *wo2p, *w1fp, *w2fp;
    cudaGetSymbolAddress((void**)&tbuf,   g_t);
    cudaGetSymbolAddress((void**)&x1,     g_x1);
    cudaGetSymbolAddress((void**)&x2,     g_x2);
    cudaGetSymbolAddress((void**)&hbuf,   g_h);
    cudaGetSymbolAddress((void**)&qkv1h,  g_qkv1h);
    cudaGetSymbolAddress((void**)&q2h,    g_q2h);
    cudaGetSymbolAddress((void**)&kv2h,   g_kv2h);
    cudaGetSymbolAddress((void**)&abuf,   g_abuf);
    cudaGetSymbolAddress((void**)&ench,   g_ench);
    cudaGetSymbolAddress((void**)&wqkv1p, g_wqkv1p);
    cudaGetSymbolAddress((void**)&wo1p,   g_wo1p);
    cudaGetSymbolAddress((void**)&wq2p,   g_wq2p);
    cudaGetSymbolAddress((void**)&wkv2p,  g_wkv2p);
    cudaGetSymbolAddress((void**)&wo2p,   g_wo2p);
    cudaGetSymbolAddress((void**)&w1fp,   g_w1fp);
    cudaGetSymbolAddress((void**)&w2fp,   g_w2fp);

    __half* hidden = (__half*)hbuf;   // [MTOK][4096] fp16

    cudaFuncSetAttribute(gemm_mma<false, false, 1, true>,
                         cudaFuncAttributeMaxDynamicSharedMemorySize, GSMEM);
    cudaFuncSetAttribute(gemm_mma<false, false, 1, false>,
                         cudaFuncAttributeMaxDynamicSharedMemorySize, GSMEM);
    cudaFuncSetAttribute(gemm_mma<false, true, 0, false>,
                         cudaFuncAttributeMaxDynamicSharedMemorySize, GSMEM);
    cudaFuncSetAttribute(gemm_mma<true, false, 1, false>,
                         cudaFuncAttributeMaxDynamicSharedMemorySize, GSMEM);
    cudaFuncSetAttribute(attn_h,
                         cudaFuncAttributeMaxDynamicSharedMemorySize, ASMEM);

    // ---- Weight conversion jobs (shared) ----
    WJobs jobs;
    auto mk = [](const float* X, __half* Y, int K, int Nin, int rowOff,
                 long hStride, int heads) {
        WJob j;
        j.X = X; j.Y = Y; j.K = K; j.Nin = Nin; j.rowOff = rowOff;
        j.tilesX = Nin / 32;
        j.tilesPerHead = (Nin / 32) * (K / 32);
        j.count = j.tilesPerHead * heads;
        j.hStride = hStride;
        return j;
    };
    jobs.j[0] = mk(Wq1, wqkv1p, 1024, 64, 0,    65536, 16);
    jobs.j[1] = mk(Wk1, wqkv1p, 1024, 64, 1024, 65536, 16);
    jobs.j[2] = mk(Wv1, wqkv1p, 1024, 64, 2048, 65536, 16);
    jobs.j[3] = mk(Wo1, wo1p,  1024, 1024, 0, 0, 1);
    jobs.j[4] = mk(Wq2, wq2p,  1024, 64, 0,    65536, 16);
    jobs.j[5] = mk(Wk2, wkv2p, 1024, 64, 0,    65536, 16);
    jobs.j[6] = mk(Wv2, wkv2p, 1024, 64, 1024, 65536, 16);
    jobs.j[7] = mk(Wo2, wo2p,  1024, 1024, 0, 0, 1);
    jobs.j[8] = mk(W1f, w1fp,  1024, 4096, 0, 0, 1);
    jobs.j[9] = mk(W2f, w2fp,  4096, 1024, 0, 0, 1);
    int total = 0;
    for (int i = 0; i < 10; i++) total += jobs.j[i].count;

    cudaStream_t s1;
    cudaStreamCreateWithFlags(&s1, cudaStreamNonBlocking);
    cudaEvent_t evFork, evJoin;
    cudaEventCreateWithFlags(&evFork, cudaEventDisableTiming);
    cudaEventCreateWithFlags(&evJoin, cudaEventDisableTiming);

    convw<<<total, 256>>>(jobs);
    cudaEventRecord(evFork, 0);
    cudaStreamWaitEvent(s1, evFork, 0);

    // One half-chain (2048 rows = 2 batches), stream-parametrized
    auto half_chain = [&](int r0, cudaStream_t st) {
        const size_t o1 = (size_t)r0 * 1024;
        const size_t o2 = (size_t)r0 * 2048;
        const size_t o3 = (size_t)r0 * 3072;
        const size_t o4 = (size_t)r0 * 4096;

        converta<<<1024, 256, 0, st>>>(x + o1, abuf + o1);
        converta<<<1024, 256, 0, st>>>(enc + o1, ench + o1);

        // QKV projection (half): 128x128 tiles -> dim3(16, 24)
        gemm_mma<false, false, 1, true><<<dim3(16, 24), 256, GSMEM, st>>>(
            abuf + o1, wqkv1p, bq1, bk1, bv1, nullptr, nullptr,
            qkv1h + o3, 3072, 1024, 3072);
        // KV2
        gemm_mma<false, false, 1, true><<<dim3(16, 16), 256, GSMEM, st>>>(
            ench + o1, wkv2p, bk2, bv2, bv2, nullptr, nullptr,
            kv2h + o2, 2048, 1024, 2048);

        // Self-attention (2 batches, 128-row Q tiles -> dim3(8, 32))
        attn_h<<<dim3(8, 32), 256, ASMEM, st>>>(
            qkv1h + o3, 3072, qkv1h + o3 + 1024, 3072,
            qkv1h + o3 + 2048, 3072, abuf + o1, 1);
        gemm_mma<false, true, 0, false><<<dim3(16, 8), 256, GSMEM, st>>>(
            abuf + o1, wo1p, bo1, nullptr, nullptr, x + o1,
            tbuf + o1, nullptr, 1024, 1024, 0);
        ln_k<<<2048, 256, 0, st>>>(tbuf + o1, g1, be1, x1 + o1, abuf + o1);

        // Cross-attention
        gemm_mma<false, false, 1, false><<<dim3(16, 8), 256, GSMEM, st>>>(
            abuf + o1, wq2p, bq2, nullptr, nullptr, nullptr, nullptr,
            q2h + o1, 1024, 1024, 1024);
        attn_h<<<dim3(8, 32), 256, ASMEM, st>>>(
            q2h + o1, 1024, kv2h + o2, 2048,
            kv2h + o2 + 1024, 2048, abuf + o1, 0);
        gemm_mma<false, true, 0, false><<<dim3(16, 8), 256, GSMEM, st>>>(
            abuf + o1, wo2p, bo2, nullptr, nullptr, x1 + o1,
            tbuf + o1, nullptr, 1024, 1024, 0);
        ln_k<<<2048, 256, 0, st>>>(tbuf + o1, g2, be2, x2 + o1, abuf + o1);

        // FFN
        gemm_mma<true, false, 1, false><<<dim3(16, 32), 256, GSMEM, st>>>(
            abuf + o1, w1fp, b1f, nullptr, nullptr, nullptr, nullptr,
            hidden + o4, 4096, 1024, 4096);
        gemm_mma<false, true, 0, false><<<dim3(16, 8), 256, GSMEM, st>>>(
            hidden + o4, w2fp, b2f, nullptr, nullptr, x2 + o1,
            tbuf + o1, nullptr, 1024, 4096, 0);
        ln_k<<<2048, 256, 0, st>>>(tbuf + o1, g3, be3, out + o1, nullptr);
    };

    half_chain(0, (cudaStream_t)0);
    half_chain(2048, s1);

    cudaEventRecord(evJoin, s1);
    cudaStreamWaitEvent(0, evJoin, 0);
}

// round 17
// speedup vs baseline: 1.1772x; 1.0171x over previous
#include <cuda_runtime.h>
#include <cuda_fp16.h>
#include <cstdint>

// Problem constants
#define BN   4
#define SN   1024
#define MTOK (BN * SN)   // 4096

// ---------------------------------------------------------------------------
// Device scratch
// ---------------------------------------------------------------------------
__device__ float g_t    [MTOK * 1024];
__device__ float g_x1   [MTOK * 1024];
__device__ float g_x2   [MTOK * 1024];
__device__ float g_h    [MTOK * 4096];   // reused as half[MTOK*4096] (hidden)

__device__ __half g_qkv1h[MTOK * 3072];
__device__ __half g_q2h  [MTOK * 1024];
__device__ __half g_kv2h [MTOK * 2048];
__device__ __half g_abuf [MTOK * 1024];
__device__ __half g_ench [MTOK * 1024];

// fp16 weights (transposed to [N x K] row-major)
__device__ __half g_wqkv1p[3072 * 1024];
__device__ __half g_wo1p  [1024 * 1024];
__device__ __half g_wq2p  [1024 * 1024];
__device__ __half g_wkv2p [2048 * 1024];
__device__ __half g_wo2p  [1024 * 1024];
__device__ __half g_w1fp  [4096 * 1024];
__device__ __half g_w2fp  [1024 * 4096];

// ---------------------------------------------------------------------------
// PTX helpers
// ---------------------------------------------------------------------------
__device__ __forceinline__ uint32_t smem_u32(const void* p) {
    uint32_t a;
    asm("{ .reg .u64 t; cvta.to.shared.u64 t, %1; cvt.u32.u64 %0, t; }"
        : "=r"(a) : "l"(p));
    return a;
}

__device__ __forceinline__ void cpasync16(uint32_t dst, const void* src) {
    asm volatile("cp.async.cg.shared.global [%0], [%1], 16;"
                 :: "r"(dst), "l"(src));
}

__device__ __forceinline__ void ldsm4(uint32_t& r0, uint32_t& r1,
                                      uint32_t& r2, uint32_t& r3, uint32_t a) {
    asm volatile("ldmatrix.sync.aligned.m8n8.x4.shared.b16 {%0,%1,%2,%3}, [%4];"
                 : "=r"(r0), "=r"(r1), "=r"(r2), "=r"(r3) : "r"(a));
}

__device__ __forceinline__ void ldsm4t(uint32_t& r0, uint32_t& r1,
                                       uint32_t& r2, uint32_t& r3, uint32_t a) {
    asm volatile("ldmatrix.sync.aligned.m8n8.x4.trans.shared.b16 {%0,%1,%2,%3}, [%4];"
                 : "=r"(r0), "=r"(r1), "=r"(r2), "=r"(r3) : "r"(a));
}

__device__ __forceinline__ void mma16816(float* c, const uint32_t* a,
                                         uint32_t b0, uint32_t b1) {
    asm volatile(
        "mma.sync.aligned.m16n8k16.row.col.f32.f16.f16.f32 "
        "{%0,%1,%2,%3}, {%4,%5,%6,%7}, {%8,%9}, {%0,%1,%2,%3};"
        : "+f"(c[0]), "+f"(c[1]), "+f"(c[2]), "+f"(c[3])
        : "r"(a[0]), "r"(a[1]), "r"(a[2]), "r"(a[3]), "r"(b0), "r"(b1));
}

__device__ __forceinline__ uint32_t packh2(float a, float b) {
    __half2 h = __floats2half2_rn(a, b);
    return *(uint32_t*)&h;
}

// ---------------------------------------------------------------------------
// Batched weight transpose+convert: 10 jobs in ONE launch.
// ---------------------------------------------------------------------------
struct WJob {
    const float* X; __half* Y;
    int K, Nin, rowOff, tilesX, tilesPerHead, count;
    long hStride;
};
struct WJobs { WJob j[10]; };

__global__ __launch_bounds__(256)
void convw(WJobs jobs) {
    int t = blockIdx.x;
    int i = 0;
    while (i < 9 && t >= jobs.j[i].count) { t -= jobs.j[i].count; i++; }
    const WJob jb = jobs.j[i];
    const int h = t / jb.tilesPerHead;
    const int rem = t % jb.tilesPerHead;
    const int ky = rem / jb.tilesX, nx = rem % jb.tilesX;
    const float* X = jb.X + (long)h * jb.hStride;
    const int rowOff = jb.rowOff + h * jb.Nin;
    const int n0 = nx * 32, k0 = ky * 32;

    __shared__ float tl[32][33];
    const int tx = threadIdx.x & 31, ty = threadIdx.x >> 5;
#pragma unroll
    for (int r = 0; r < 4; r++)
        tl[ty + 8 * r][tx] = X[(long)(k0 + ty + 8 * r) * jb.Nin + n0 + tx];
    __syncthreads();
#pragma unroll
    for (int r = 0; r < 4; r++) {
        const int n = n0 + ty + 8 * r, k = k0 + tx;
        jb.Y[(long)(rowOff + n) * jb.K + k] = __float2half_rn(tl[tx][ty + 8 * r]);
    }
}

// ---------------------------------------------------------------------------
// Convert activations: X fp32 [n] -> Y fp16 [n]
// ---------------------------------------------------------------------------
__global__ __launch_bounds__(256)
void converta(const float* __restrict__ X, __half* __restrict__ Y) {
    const size_t i = ((size_t)blockIdx.x * 256 + threadIdx.x) << 3;
    float4 a = *(const float4*)&X[i];
    float4 b = *(const float4*)&X[i + 4];
    __half2 h0 = __floats2half2_rn(a.x, a.y);
    __half2 h1 = __floats2half2_rn(a.z, a.w);
    __half2 h2 = __floats2half2_rn(b.x, b.y);
    __half2 h3 = __floats2half2_rn(b.z, b.w);
    uint4 u;
    u.x = *(unsigned*)&h0; u.y = *(unsigned*)&h1;
    u.z = *(unsigned*)&h2; u.w = *(unsigned*)&h3;
    *(uint4*)&Y[i] = u;
}

// ---------------------------------------------------------------------------
// HMMA fp16 GEMM (proven optimum): CTA 128x128, warptile 64x32,
// K-step 64, 3-stage cp.async, 2 CTAs/SM.
// ---------------------------------------------------------------------------
#define SMP 72
#define STGH (128 * SMP)
#define GSMEM (3 * 2 * STGH * 2)   // 110592 B

template<bool RELU, bool RES, int OUT, bool SEG>
__global__ __launch_bounds__(256, 2)
void gemm_mma(const __half* __restrict__ A, const __half* __restrict__ Bw,
              const float* __restrict__ b0, const float* __restrict__ b1v,
              const float* __restrict__ b2, const float* __restrict__ R,
              float* __restrict__ C32, __half* __restrict__ C16,
              int N, int Kp, int P2) {
    extern __shared__ __half smh[];
    __half* As = smh;
    __half* Bs = smh + 3 * STGH;

    const int tid = threadIdx.x, lane = tid & 31, warp = tid >> 5;
    const int m0 = blockIdx.x * 128, n0 = blockIdx.y * 128;
    const int wm = (warp & 1) * 64, wn = (warp >> 1) * 32;

    const uint32_t asb = smem_u32(As);
    const uint32_t bsb = smem_u32(Bs);
    const __half* Ab = A + (size_t)m0 * Kp;
    const __half* Bb = Bw + (size_t)n0 * Kp;

    float acc[4][4][4];
#pragma unroll
    for (int i = 0; i < 4; i++)
#pragma unroll
        for (int j = 0; j < 4; j++)
#pragma unroll
            for (int k = 0; k < 4; k++) acc[i][j][k] = 0.f;

#define LOAD_STAGE(s, k0) do {                                                  \
        _Pragma("unroll")                                                       \
        for (int i_ = 0; i_ < 4; i_++) {                                        \
            int idx_ = tid + (i_ << 8);                                         \
            int rr_ = idx_ >> 3, sg_ = idx_ & 7;                                \
            uint32_t so_ = (uint32_t)(((s) * STGH + rr_ * SMP + sg_ * 8) * 2);  \
            size_t go_ = (size_t)rr_ * Kp + (size_t)(k0) + sg_ * 8;             \
            cpasync16(asb + so_, Ab + go_);                                     \
            cpasync16(bsb + so_, Bb + go_);                                     \
        }                                                                       \
        asm volatile("cp.async.commit_group;" ::: "memory");                    \
    } while (0)

    const int nst = Kp >> 6;
    LOAD_STAGE(0, 0);
    LOAD_STAGE(1, 64);

    int s = 0, sn = 2;
    for (int kt = 0; kt < nst; kt++) {
        if (kt + 1 < nst)
            asm volatile("cp.async.wait_group 1;" ::: "memory");
        else
            asm volatile("cp.async.wait_group 0;" ::: "memory");
        __syncthreads();

        if (kt + 2 < nst) {
            LOAD_STAGE(sn, (kt + 2) << 6);
            sn = (sn == 2) ? 0 : sn + 1;
        }

        const uint32_t sA = asb + (uint32_t)(s * STGH * 2);
        const uint32_t sB = bsb + (uint32_t)(s * STGH * 2);
        s = (s == 2) ? 0 : s + 1;

#pragma unroll
        for (int kk = 0; kk < 4; kk++) {
            uint32_t aF[4][4], bF[2][4];
#pragma unroll
            for (int mt = 0; mt < 4; mt++) {
                uint32_t ad = sA + (uint32_t)(((wm + mt * 16 + (lane & 15)) * SMP
                                  + kk * 16 + (lane >> 4) * 8) * 2);
                ldsm4(aF[mt][0], aF[mt][1], aF[mt][2], aF[mt][3], ad);
            }
#pragma unroll
            for (int g = 0; g < 2; g++) {
                int nr = wn + g * 16 + (lane & 7) + ((lane >> 4) << 3);
                int kc = kk * 16 + ((lane >> 3) & 1) * 8;
                uint32_t bd = sB + (uint32_t)((nr * SMP + kc) * 2);
                ldsm4(bF[g][0], bF[g][1], bF[g][2], bF[g][3], bd);
            }
#pragma unroll
            for (int mt = 0; mt < 4; mt++)
#pragma unroll
                for (int nt = 0; nt < 4; nt++)
                    mma16816(acc[mt][nt], aF[mt],
                             bF[nt >> 1][(nt & 1) * 2],
                             bF[nt >> 1][(nt & 1) * 2 + 1]);
        }
    }
#undef LOAD_STAGE

    const float* bias = b0;
    int cb0 = n0;
    if (SEG) {
        const int sg = n0 >> 10;
        bias = (sg == 0) ? b0 : ((sg == 1) ? b1v : b2);
        cb0 = n0 & 1023;
    }

#pragma unroll
    for (int mt = 0; mt < 4; mt++) {
        const int r0 = m0 + wm + mt * 16 + (lane >> 2);
#pragma unroll
        for (int nt = 0; nt < 4; nt++) {
            const int cl = wn + nt * 8 + ((lane & 3) << 1);
            const int c = n0 + cl;
            float2 bv = *(const float2*)&bias[cb0 + cl];
            float2 v0, v1;
            v0.x = acc[mt][nt][0] + bv.x; v0.y = acc[mt][nt][1] + bv.y;
            v1.x = acc[mt][nt][2] + bv.x; v1.y = acc[mt][nt][3] + bv.y;
            if (RES) {
                float2 ra = *(const float2*)&R[(size_t)r0 * N + c];
                float2 rb = *(const float2*)&R[(size_t)(r0 + 8) * N + c];
                v0.x += ra.x; v0.y += ra.y;
                v1.x += rb.x; v1.y += rb.y;
            }
            if (RELU) {
                v0.x = fmaxf(v0.x, 0.f); v0.y = fmaxf(v0.y, 0.f);
                v1.x = fmaxf(v1.x, 0.f); v1.y = fmaxf(v1.y, 0.f);
            }
            if (OUT == 0) {
                *(float2*)&C32[(size_t)r0 * N + c] = v0;
                *(float2*)&C32[(size_t)(r0 + 8) * N + c] = v1;
            } else {
                __half2 h0 = __floats2half2_rn(v0.x, v0.y);
                __half2 h1 = __floats2half2_rn(v1.x, v1.y);
                *(__half2*)&C16[(size_t)r0 * P2 + c] = h0;
                *(__half2*)&C16[(size_t)(r0 + 8) * P2 + c] = h1;
            }
        }
    }
}

// ---------------------------------------------------------------------------
// HMMA fp16 flash attention: 128 queries/block, 256 threads (8 warps),
// double-buffered cp.async K/V. Dynamic SMEM 55296 B.
// ---------------------------------------------------------------------------
#define ASMEM ((128 + 4 * 64) * 72 * 2)

__global__ __launch_bounds__(256)
void attn_h(const __half* __restrict__ Qp, int ldq,
            const __half* __restrict__ Kp, int ldk,
            const __half* __restrict__ Vp, int ldv,
            __half* __restrict__ Op, int causal) {
    extern __shared__ __half asm_[];
    __half* Qs = asm_;
    __half* Ks = asm_ + 128 * 72;
    __half* Vs = asm_ + (128 + 2 * 64) * 72;

    const int tid = threadIdx.x, lane = tid & 31, warp = tid >> 5;
    const int q0 = blockIdx.x * 128;
    const int b = blockIdx.y >> 4, h = blockIdx.y & 15;

    const __half* qb = Qp + (size_t)(b * SN) * ldq + h * 64;
    const __half* kb = Kp + (size_t)(b * SN) * ldk + h * 64;
    const __half* vb = Vp + (size_t)(b * SN) * ldv + h * 64;

    const uint32_t ksb = smem_u32(Ks);
    const uint32_t vsb = smem_u32(Vs);

#define ATTN_LOAD(s, kt) do {                                                  \
        _Pragma("unroll")                                                      \
        for (int i_ = 0; i_ < 2; i_++) {                                       \
            int idx_ = tid + i_ * 256;                                         \
            int r_ = idx_ >> 3, sg_ = idx_ & 7;                                \
            uint32_t off_ = (uint32_t)(((s) * 64 * 72 + r_ * 72 + sg_ * 8) * 2); \
            cpasync16(ksb + off_, kb + (size_t)((kt) * 64 + r_) * ldk + sg_ * 8); \
            cpasync16(vsb + off_, vb + (size_t)((kt) * 64 + r_) * ldv + sg_ * 8); \
        }                                                                      \
        asm volatile("cp.async.commit_group;" ::: "memory");                   \
    } while (0)

    ATTN_LOAD(0, 0);

#pragma unroll
    for (int i = 0; i < 4; i++) {
        int idx = tid + i * 256;
        int r = idx >> 3, sg = idx & 7;
        *(uint4*)&Qs[r * 72 + sg * 8] =
            *(const uint4*)&qb[(size_t)(q0 + r) * ldq + sg * 8];
    }
    __syncthreads();

    uint32_t aQ[4][4];
#pragma unroll
    for (int kc = 0; kc < 4; kc++) {
        uint32_t ad = smem_u32(&Qs[(warp * 16 + (lane & 15)) * 72
                                   + kc * 16 + (lane >> 4) * 8]);
        ldsm4(aQ[kc][0], aQ[kc][1], aQ[kc][2], aQ[kc][3], ad);
    }

    float m0 = -1e30f, m1 = -1e30f, l0 = 0.f, l1 = 0.f;
    float o[8][4];
#pragma unroll
    for (int j = 0; j < 8; j++)
#pragma unroll
        for (int e = 0; e < 4; e++) o[j][e] = 0.f;

    const int nkt = causal ? (q0 >> 6) + 2 : 16;
    const int grow0 = q0 + warp * 16 + (lane >> 2);
    int buf = 0;
    for (int kt = 0; kt < nkt; kt++) {
        asm volatile("cp.async.wait_group 0;" ::: "memory");
        __syncthreads();

        if (kt + 1 < nkt)
            ATTN_LOAD(buf ^ 1, kt + 1);

        float c[8][4];
#pragma unroll
        for (int j = 0; j < 8; j++)
#pragma unroll
            for (int e = 0; e < 4; e++) c[j][e] = 0.f;
#pragma unroll
        for (int kc = 0; kc < 4; kc++)
#pragma unroll
            for (int g = 0; g < 4; g++) {
                uint32_t b0, b1, b2, b3;
                uint32_t bd = smem_u32(&Ks[buf * 64 * 72
                                   + (g * 16 + (lane & 7) + ((lane >> 4) << 3)) * 72
                                   + kc * 16 + ((lane >> 3) & 1) * 8]);
                ldsm4(b0, b1, b2, b3, bd);
                mma16816(c[2 * g], aQ[kc], b0, b1);
                mma16816(c[2 * g + 1], aQ[kc], b2, b3);
            }
#pragma unroll
        for (int j = 0; j < 8; j++)
#pragma unroll
            for (int e = 0; e < 4; e++) c[j][e] *= 0.125f;

        if (causal && kt * 64 + 63 > grow0 - 8) {
            const int r0g = grow0, r1g = grow0 + 8;
#pragma unroll
            for (int j = 0; j < 8; j++) {
                int gc = kt * 64 + 8 * j + ((lane & 3) << 1);
                if (gc     > r0g) c[j][0] = -1e30f;
                if (gc + 1 > r0g) c[j][1] = -1e30f;
                if (gc     > r1g) c[j][2] = -1e30f;
                if (gc + 1 > r1g) c[j][3] = -1e30f;
            }
        }

        float rm0 = -1e30f, rm1 = -1e30f;
#pragma unroll
        for (int j = 0; j < 8; j++) {
            rm0 = fmaxf(rm0, fmaxf(c[j][0], c[j][1]));
            rm1 = fmaxf(rm1, fmaxf(c[j][2], c[j][3]));
        }
        rm0 = fmaxf(rm0, __shfl_xor_sync(0xffffffffu, rm0, 1));
        rm0 = fmaxf(rm0, __shfl_xor_sync(0xffffffffu, rm0, 2));
        rm1 = fmaxf(rm1, __shfl_xor_sync(0xffffffffu, rm1, 1));
        rm1 = fmaxf(rm1, __shfl_xor_sync(0xffffffffu, rm1, 2));
        float mn0 = fmaxf(m0, rm0), mn1 = fmaxf(m1, rm1);
        float al0 = __expf(m0 - mn0), al1 = __expf(m1 - mn1);
        m0 = mn0; m1 = mn1;
        float rs0 = 0.f, rs1 = 0.f;
#pragma unroll
        for (int j = 0; j < 8; j++) {
            c[j][0] = __expf(c[j][0] - mn0);
            c[j][1] = __expf(c[j][1] - mn0);
            c[j][2] = __expf(c[j][2] - mn1);
            c[j][3] = __expf(c[j][3] - mn1);
            rs0 += c[j][0] + c[j][1];
            rs1 += c[j][2] + c[j][3];
        }
        rs0 += __shfl_xor_sync(0xffffffffu, rs0, 1);
        rs0 += __shfl_xor_sync(0xffffffffu, rs0, 2);
        rs1 += __shfl_xor_sync(0xffffffffu, rs1, 1);
        rs1 += __shfl_xor_sync(0xffffffffu, rs1, 2);
        l0 = l0 * al0 + rs0;
        l1 = l1 * al1 + rs1;
#pragma unroll
        for (int j = 0; j < 8; j++) {
            o[j][0] *= al0; o[j][1] *= al0;
            o[j][2] *= al1; o[j][3] *= al1;
        }

#pragma unroll
        for (int kc = 0; kc < 4; kc++) {
            uint32_t aP[4];
            aP[0] = packh2(c[2 * kc][0], c[2 * kc][1]);
            aP[1] = packh2(c[2 * kc][2], c[2 * kc][3]);
            aP[2] = packh2(c[2 * kc + 1][0], c[2 * kc + 1][1]);
            aP[3] = packh2(c[2 * kc + 1][2], c[2 * kc + 1][3]);
#pragma unroll
            for (int g = 0; g < 4; g++) {
                uint32_t b0, b1, b2, b3;
                uint32_t bd = smem_u32(&Vs[buf * 64 * 72
                                   + (kc * 16 + (lane & 15)) * 72
                                   + g * 16 + (lane >> 4) * 8]);
                ldsm4t(b0, b1, b2, b3, bd);
                mma16816(o[2 * g], aP, b0, b1);
                mma16816(o[2 * g + 1], aP, b2, b3);
            }
        }
        buf ^= 1;
    }
#undef ATTN_LOAD

    float i0 = 1.f / l0, i1 = 1.f / l1;
    const int r0 = q0 + warp * 16 + (lane >> 2);
    size_t ro0 = (size_t)(b * SN + r0) * 1024 + h * 64;
    size_t ro1 = ro0 + (size_t)8 * 1024;
#pragma unroll
    for (int j = 0; j < 8; j++) {
        int cl = 8 * j + ((lane & 3) << 1);
        *(__half2*)&Op[ro0 + cl] = __floats2half2_rn(o[j][0] * i0, o[j][1] * i0);
        *(__half2*)&Op[ro1 + cl] = __floats2half2_rn(o[j][2] * i1, o[j][3] * i1);
    }
}

// ---------------------------------------------------------------------------
// LayerNorm; optional plain fp16 side-output (pitch 1024)
// ---------------------------------------------------------------------------
__global__ __launch_bounds__(256)
void ln_k(const float* __restrict__ X, const float* __restrict__ g,
          const float* __restrict__ be, float* __restrict__ Y,
          __half* __restrict__ S) {
    const int row = blockIdx.x;
    const int tid = threadIdx.x;
    const unsigned lane = tid & 31, warp = tid >> 5;

    __shared__ float red[8];
    __shared__ float stat[2];

    float4 v = *(const float4*)&X[(size_t)row * 1024 + tid * 4];
    float s = v.x + v.y + v.z + v.w;
#pragma unroll
    for (int off = 16; off; off >>= 1) s += __shfl_xor_sync(0xffffffffu, s, off);
    if (lane == 0) red[warp] = s;
    __syncthreads();
    if (tid == 0) {
        float t = 0.f;
#pragma unroll
        for (int i = 0; i < 8; i++) t += red[i];
        stat[0] = t * (1.f / 1024.f);
    }
    __syncthreads();
    const float mean = stat[0];
    float dx = v.x - mean, dy = v.y - mean, dz = v.z - mean, dw = v.w - mean;
    float sq = dx * dx + dy * dy + dz * dz + dw * dw;
#pragma unroll
    for (int off = 16; off; off >>= 1) sq += __shfl_xor_sync(0xffffffffu, sq, off);
    if (lane == 0) red[warp] = sq;
    __syncthreads();
    if (tid == 0) {
        float t = 0.f;
#pragma unroll
        for (int i = 0; i < 8; i++) t += red[i];
        stat[1] = rsqrtf(t * (1.f / 1024.f) + 1e-5f);
    }
    __syncthreads();
    const float rstd = stat[1];
    const int c = tid * 4;
    float4 gv = *(const float4*)&g[c];
    float4 bv = *(const float4*)&be[c];
    float4 r;
    r.x = gv.x * dx * rstd + bv.x;
    r.y = gv.y * dy * rstd + bv.y;
    r.z = gv.z * dz * rstd + bv.z;
    r.w = gv.w * dw * rstd + bv.w;
    *(float4*)&Y[(size_t)row * 1024 + c] = r;
    if (S) {
        __half2 H0 = __floats2half2_rn(r.x, r.y);
        __half2 H1 = __floats2half2_rn(r.z, r.w);
        uint2 hu;
        hu.x = *(unsigned*)&H0; hu.y = *(unsigned*)&H1;
        *(uint2*)&S[(size_t)row * 1024 + c] = hu;
    }
}

// ---------------------------------------------------------------------------
// Launcher: 4-way M-parallel quarter-chains; streams/events created ONCE
// (first call = correctness run) so graph capture performs no allocations.
// ---------------------------------------------------------------------------
extern "C" void kernel_launch(void* const* d_in, const int* in_sizes, int n_in,
                              void* d_out, int out_size) {
    const float* x    = (const float*)d_in[0];
    const float* enc  = (const float*)d_in[2];
    const float* Wq1  = (const float*)d_in[4];
    const float* bq1  = (const float*)d_in[5];
    const float* Wk1  = (const float*)d_in[6];
    const float* bk1  = (const float*)d_in[7];
    const float* Wv1  = (const float*)d_in[8];
    const float* bv1  = (const float*)d_in[9];
    const float* Wo1  = (const float*)d_in[10];
    const float* bo1  = (const float*)d_in[11];
    const float* Wq2  = (const float*)d_in[12];
    const float* bq2  = (const float*)d_in[13];
    const float* Wk2  = (const float*)d_in[14];
    const float* bk2  = (const float*)d_in[15];
    const float* Wv2  = (const float*)d_in[16];
    const float* bv2  = (const float*)d_in[17];
    const float* Wo2  = (const float*)d_in[18];
    const float* bo2  = (const float*)d_in[19];
    const float* W1f  = (const float*)d_in[20];
    const float* b1f  = (const float*)d_in[21];
    const float* W2f  = (const float*)d_in[22];
    const float* b2f  = (const float*)d_in[23];
    const float* g1   = (const float*)d_in[24];
    const float* be1  = (const float*)d_in[25];
    const float* g2   = (const float*)d_in[26];
    const float* be2  = (const float*)d_in[27];
    const float* g3   = (const float*)d_in[28];
    const float* be3  = (const float*)d_in[29];
    float* out = (float*)d_out;

    float *tbuf, *x1, *x2, *hbuf;
    __half *qkv1h, *q2h, *kv2h, *abuf, *ench;
    __half *wqkv1p, *wo1p, *wq2p, *wkv2p, *wo2p, *w1fp, *w2fp;
    cudaGetSymbolAddress((void**)&tbuf,   g_t);
    cudaGetSymbolAddress((void**)&x1,     g_x1);
    cudaGetSymbolAddress((void**)&x2,     g_x2);
    cudaGetSymbolAddress((void**)&hbuf,   g_h);
    cudaGetSymbolAddress((void**)&qkv1h,  g_qkv1h);
    cudaGetSymbolAddress((void**)&q2h,    g_q2h);
    cudaGetSymbolAddress((void**)&kv2h,   g_kv2h);
    cudaGetSymbolAddress((void**)&abuf,   g_abuf);
    cudaGetSymbolAddress((void**)&ench,   g_ench);
    cudaGetSymbolAddress((void**)&wqkv1p, g_wqkv1p);
    cudaGetSymbolAddress((void**)&wo1p,   g_wo1p);
    cudaGetSymbolAddress((void**)&wq2p,   g_wq2p);
    cudaGetSymbolAddress((void**)&wkv2p,  g_wkv2p);
    cudaGetSymbolAddress((void**)&wo2p,   g_wo2p);
    cudaGetSymbolAddress((void**)&w1fp,   g_w1fp);
    cudaGetSymbolAddress((void**)&w2fp,   g_w2fp);

    __half* hidden = (__half*)hbuf;   // [MTOK][4096] fp16

    cudaFuncSetAttribute(gemm_mma<false, false, 1, true>,
                         cudaFuncAttributeMaxDynamicSharedMemorySize, GSMEM);
    cudaFuncSetAttribute(gemm_mma<false, false, 1, false>,
                         cudaFuncAttributeMaxDynamicSharedMemorySize, GSMEM);
    cudaFuncSetAttribute(gemm_mma<false, true, 0, false>,
                         cudaFuncAttributeMaxDynamicSharedMemorySize, GSMEM);
    cudaFuncSetAttribute(gemm_mma<true, false, 1, false>,
                         cudaFuncAttributeMaxDynamicSharedMemorySize, GSMEM);
    cudaFuncSetAttribute(attn_h,
                         cudaFuncAttributeMaxDynamicSharedMemorySize, ASMEM);

    // ---- Weight conversion jobs (shared) ----
    WJobs jobs;
    auto mk = [](const float* X, __half* Y, int K, int Nin, int rowOff,
                 long hStride, int heads) {
        WJob j;
        j.X = X; j.Y = Y; j.K = K; j.Nin = Nin; j.rowOff = rowOff;
        j.tilesX = Nin / 32;
        j.tilesPerHead = (Nin / 32) * (K / 32);
        j.count = j.tilesPerHead * heads;
        j.hStride = hStride;
        return j;
    };
    jobs.j[0] = mk(Wq1, wqkv1p, 1024, 64, 0,    65536, 16);
    jobs.j[1] = mk(Wk1, wqkv1p, 1024, 64, 1024, 65536, 16);
    jobs.j[2] = mk(Wv1, wqkv1p, 1024, 64, 2048, 65536, 16);
    jobs.j[3] = mk(Wo1, wo1p,  1024, 1024, 0, 0, 1);
    jobs.j[4] = mk(Wq2, wq2p,  1024, 64, 0,    65536, 16);
    jobs.j[5] = mk(Wk2, wkv2p, 1024, 64, 0,    65536, 16);
    jobs.j[6] = mk(Wv2, wkv2p, 1024, 64, 1024, 65536, 16);
    jobs.j[7] = mk(Wo2, wo2p,  1024, 1024, 0, 0, 1);
    jobs.j[8] = mk(W1f, w1fp,  1024, 4096, 0, 0, 1);
    jobs.j[9] = mk(W2f, w2fp,  4096, 1024, 0, 0, 1);
    int total = 0;
    for (int i = 0; i < 10; i++) total += jobs.j[i].count;

    // Streams/events: created once, reused every call (no allocations during
    // graph capture — the first call is the correctness run).
    static cudaStream_t s1, s2, s3;
    static cudaEvent_t evFork, evCa, evCw, evJ1, evJ2, evJ3;
    static bool inited = false;
    if (!inited) {
        cudaStreamCreateWithFlags(&s1, cudaStreamNonBlocking);
        cudaStreamCreateWithFlags(&s2, cudaStreamNonBlocking);
        cudaStreamCreateWithFlags(&s3, cudaStreamNonBlocking);
        cudaEventCreateWithFlags(&evFork, cudaEventDisableTiming);
        cudaEventCreateWithFlags(&evCa, cudaEventDisableTiming);
        cudaEventCreateWithFlags(&evCw, cudaEventDisableTiming);
        cudaEventCreateWithFlags(&evJ1, cudaEventDisableTiming);
        cudaEventCreateWithFlags(&evJ2, cudaEventDisableTiming);
        cudaEventCreateWithFlags(&evJ3, cudaEventDisableTiming);
        inited = true;
    }

    // Fork FIRST (stream0 is the capture origin); side streams join via wait.
    cudaEventRecord(evFork, 0);
    cudaStreamWaitEvent(s1, evFork, 0);
    cudaStreamWaitEvent(s2, evFork, 0);
    cudaStreamWaitEvent(s3, evFork, 0);

    // convw on s1 (inside capture) concurrent with converta on stream0
    convw<<<total, 256, 0, s1>>>(jobs);
    cudaEventRecord(evCw, s1);

    converta<<<2048, 256, 0, 0>>>(x, abuf);
    converta<<<2048, 256, 0, 0>>>(enc, ench);
    cudaEventRecord(evCa, 0);

    // All chain streams need: weights (evCw) + activations (evCa)
    cudaStreamWaitEvent(0, evCw, 0);
    cudaStreamWaitEvent(s1, evCa, 0);
    cudaStreamWaitEvent(s2, evCw, 0);
    cudaStreamWaitEvent(s2, evCa, 0);
    cudaStreamWaitEvent(s3, evCw, 0);
    cudaStreamWaitEvent(s3, evCa, 0);

    // Quarter-chain (1024 rows = 1 batch)
    auto quarter_chain = [&](int r0, cudaStream_t st) {
        const size_t o1 = (size_t)r0 * 1024;
        const size_t o2 = (size_t)r0 * 2048;
        const size_t o3 = (size_t)r0 * 3072;
        const size_t o4 = (size_t)r0 * 4096;

        gemm_mma<false, false, 1, true><<<dim3(8, 24), 256, GSMEM, st>>>(
            abuf + o1, wqkv1p, bq1, bk1, bv1, nullptr, nullptr,
            qkv1h + o3, 3072, 1024, 3072);
        gemm_mma<false, false, 1, true><<<dim3(8, 16), 256, GSMEM, st>>>(
            ench + o1, wkv2p, bk2, bv2, bv2, nullptr, nullptr,
            kv2h + o2, 2048, 1024, 2048);

        attn_h<<<dim3(8, 16), 256, ASMEM, st>>>(
            qkv1h + o3, 3072, qkv1h + o3 + 1024, 3072,
            qkv1h + o3 + 2048, 3072, abuf + o1, 1);
        gemm_mma<false, true, 0, false><<<dim3(8, 8), 256, GSMEM, st>>>(
            abuf + o1, wo1p, bo1, nullptr, nullptr, x + o1,
            tbuf + o1, nullptr, 1024, 1024, 0);
        ln_k<<<1024, 256, 0, st>>>(tbuf + o1, g1, be1, x1 + o1, abuf + o1);

        gemm_mma<false, false, 1, false><<<dim3(8, 8), 256, GSMEM, st>>>(
            abuf + o1, wq2p, bq2, nullptr, nullptr, nullptr, nullptr,
            q2h + o1, 1024, 1024, 1024);
        attn_h<<<dim3(8, 16), 256, ASMEM, st>>>(
            q2h + o1, 1024, kv2h + o2, 2048,
            kv2h + o2 + 1024, 2048, abuf + o1, 0);
        gemm_mma<false, true, 0, false><<<dim3(8, 8), 256, GSMEM, st>>>(
            abuf + o1, wo2p, bo2, nullptr, nullptr, x1 + o1,
            tbuf + o1, nullptr, 1024, 1024, 0);
        ln_k<<<1024, 256, 0, st>>>(tbuf + o1, g2, be2, x2 + o1, abuf + o1);

        gemm_mma<true, false, 1, false><<<dim3(8, 32), 256, GSMEM, st>>>(
            abuf + o1, w1fp, b1f, nullptr, nullptr, nullptr, nullptr,
            hidden + o4, 4096, 1024, 4096);
        gemm_mma<false, true, 0, false><<<dim3(8, 8), 256, GSMEM, st>>>(
            hidden + o4, w2fp, b2f, nullptr, nullptr, x2 + o1,
            tbuf + o1, nullptr, 1024, 4096, 0);
        ln_k<<<1024, 256, 0, st>>>(tbuf + o1, g3, be3, out + o1, nullptr);
    };

    quarter_chain(0,    (cudaStream_t)0);
    quarter_chain(1024, s1);
    quarter_chain(2048, s2);
    quarter_chain(3072, s3);

    cudaEventRecord(evJ1, s1);
    cudaEventRecord(evJ2, s2);
    cudaEventRecord(evJ3, s3);
    cudaStreamWaitEvent(0, evJ1, 0);
    cudaStreamWaitEvent(0, evJ2, 0);
    cudaStreamWaitEvent(0, evJ3, 0);
}